// round 5
// baseline (speedup 1.0000x reference)
#include <cuda_runtime.h>
#include <math_constants.h>

#define K 8
#define D 8
#define TRI 36              // D*(D+1)/2 (logical)
#define PHI_DIM 360         // K + K*D + K*TRI
#define M_MODELS 32
#define N_POINTS 32768
#define CHUNKS 32
#define THREADS 256
#define NPAIR 2             // 2 packed pairs = 4 points per thread
// padded per-k layout (ull units): tri rows at i*8 (8 ull each, zero-padded),
// bias at 64..71, const at 72, pad to 74 for clean strides
#define PSTRIDE 74

typedef unsigned long long ull;

// Scratch (no allocations allowed)
__device__ float g_partial[M_MODELS * CHUNKS];
__device__ int   g_count[M_MODELS];          // zero-init; self-resetting

__host__ __device__ __forceinline__ constexpr int tidx(int i, int j) {
    return i * (i + 1) / 2 + j;
}

// ---- packed f32x2 helpers ---------------------------------------------------
__device__ __forceinline__ ull pk2(float lo, float hi) {
    ull r; asm("mov.b64 %0,{%1,%2};" : "=l"(r) : "f"(lo), "f"(hi)); return r;
}
__device__ __forceinline__ void up2(ull v, float& lo, float& hi) {
    asm("mov.b64 {%0,%1},%2;" : "=f"(lo), "=f"(hi) : "l"(v));
}
__device__ __forceinline__ ull fma2(ull a, ull b, ull c) {
    ull r; asm("fma.rn.f32x2 %0,%1,%2,%3;" : "=l"(r) : "l"(a), "l"(b), "l"(c)); return r;
}
__device__ __forceinline__ float ex2a(float x) {
    float r; asm("ex2.approx.ftz.f32 %0,%1;" : "=f"(r) : "f"(x)); return r;
}
__device__ __forceinline__ float lg2a(float x) {
    float r; asm("lg2.approx.ftz.f32 %0,%1;" : "=f"(r) : "f"(x)); return r;
}

// ---------------------------------------------------------------------------
// Single fused kernel. grid = 1024 blocks x 256 threads, 4 CTAs/SM.
// ---------------------------------------------------------------------------
__global__ void __launch_bounds__(THREADS, 4) fused_kernel(const float* __restrict__ phi,
                                                           const float* __restrict__ X,
                                                           float* __restrict__ out) {
    const int m = blockIdx.x >> 5;
    const int chunk = blockIdx.x & (CHUNKS - 1);
    const int tid = threadIdx.x;
    const float* pm = phi + m * PHI_DIM;

    __shared__ ull sp[K * PSTRIDE];
    __shared__ float red[THREADS];
    __shared__ float redp[THREADS];

    // ---- prior partial -------------------------------------------------------
    float pp = 0.f;
    #pragma unroll
    for (int i = tid; i < PHI_DIM; i += THREADS) {
        float v = pm[i];
        pp = fmaf(v, v, pp);
    }
    redp[tid] = pp;

    // zero the padded param block (pads must be exactly 0)
    #pragma unroll
    for (int i = tid; i < K * PSTRIDE; i += THREADS) sp[i] = 0ull;
    __syncthreads();

    // ---- Stage A: build params in shared (threads 0-63, column-parallel) ----
    if (tid < 64) {
        const int k = tid >> 3;
        const int j = tid & 7;
        const float* Lk = pm + K + K * D + k * TRI;
        ull* dst = sp + k * PSTRIDE;
        const float SCALE = 0.8493218002880191f;  // sqrt(0.5*log2(e))

        float col[D];
        col[j] = __fdividef(1.f, Lk[tidx(j, j)]);
        for (int i = j + 1; i < D; ++i) {
            float acc = 0.f;
            for (int p = j; p < i; ++p)
                acc = fmaf(Lk[tidx(i, p)], col[p], acc);
            col[i] = -acc * __fdividef(1.f, Lk[tidx(i, i)]);
        }
        for (int i = j; i < D; ++i) {
            float v = col[i] * SCALE;
            dst[i * 8 + j] = pk2(v, v);     // row-padded layout
        }

        if (j == 0) {
            float mx = -CUDART_INF_F;
            #pragma unroll
            for (int q = 0; q < K; ++q) mx = fmaxf(mx, pm[q]);
            float s = 0.f;
            #pragma unroll
            for (int q = 0; q < K; ++q) s += __expf(pm[q] - mx);
            const float log_pi = pm[k] - mx - __logf(s);

            float ld = 0.f;
            #pragma unroll
            for (int i = 0; i < D; ++i)
                ld += __logf(fmaxf(fabsf(Lk[tidx(i, i)]), 1e-8f));
            ld *= 2.f;

            const float c = log_pi - 0.5f * (D * 1.8378770664093453f + ld);
            const float c2 = c * 1.4426950408889634f;
            dst[72] = pk2(c2, c2);
        }
    }
    __syncthreads();

    // bias: nb_i = -sum_{j<=i} Linv_scaled[i][j] * mu[j]   (thread (k,i))
    if (tid < 64) {
        const int k = tid >> 3;
        const int i = tid & 7;
        const float* mu = pm + K + k * D;
        ull* dst = sp + k * PSTRIDE;
        float b = 0.f;
        for (int j = 0; j <= i; ++j) {
            float lo, hi;
            up2(dst[i * 8 + j], lo, hi);
            b = fmaf(lo, mu[j], b);
        }
        float nb = -b;
        dst[64 + i] = pk2(nb, nb);
    }
    __syncthreads();

    // ---- Stage B: main loop --------------------------------------------------
    const float4* __restrict__ X4 = reinterpret_cast<const float4*>(X);
    const int n0 = chunk * (N_POINTS / CHUNKS) + tid;

    // 4 points as 2 pairs: (n0, n0+256), (n0+512, n0+768)
    ull xp[NPAIR][D];
    #pragma unroll
    for (int pr = 0; pr < NPAIR; ++pr) {
        const int na = n0 + (2 * pr) * THREADS;
        const int nb = na + THREADS;
        float4 a0 = X4[2 * na], a1 = X4[2 * na + 1];
        float4 b0 = X4[2 * nb], b1 = X4[2 * nb + 1];
        xp[pr][0] = pk2(a0.x, b0.x); xp[pr][1] = pk2(a0.y, b0.y);
        xp[pr][2] = pk2(a0.z, b0.z); xp[pr][3] = pk2(a0.w, b0.w);
        xp[pr][4] = pk2(a1.x, b1.x); xp[pr][5] = pk2(a1.y, b1.y);
        xp[pr][6] = pk2(a1.z, b1.z); xp[pr][7] = pk2(a1.w, b1.w);
    }

    float mx[2 * NPAIR], sm[2 * NPAIR];
    #pragma unroll
    for (int p = 0; p < 2 * NPAIR; ++p) { mx[p] = -CUDART_INF_F; sm[p] = 0.f; }

    #pragma unroll 1
    for (int k = 0; k < K; ++k) {
        const ull* __restrict__ w = sp + k * PSTRIDE;
        float c2, c2h;
        up2(w[72], c2, c2h);

        ull maha0 = 0ull, maha1 = 0ull;
        #pragma unroll
        for (int i = 0; i < D; ++i) {
            const ull nb = w[64 + i];              // bias init
            ull a0 = nb, a1 = nb;
            const ulonglong2* __restrict__ wr =
                reinterpret_cast<const ulonglong2*>(w + i * 8);
            #pragma unroll
            for (int jp = 0; jp <= (i >> 1); ++jp) {   // ull pairs; pads are 0
                const ulonglong2 v = wr[jp];
                a0 = fma2(v.x, xp[0][2 * jp], a0);
                a1 = fma2(v.x, xp[1][2 * jp], a1);
                a0 = fma2(v.y, xp[0][2 * jp + 1], a0);
                a1 = fma2(v.y, xp[1][2 * jp + 1], a1);
            }
            maha0 = fma2(a0, a0, maha0);
            maha1 = fma2(a1, a1, maha1);
        }

        float mm[4];
        up2(maha0, mm[0], mm[1]);
        up2(maha1, mm[2], mm[3]);
        #pragma unroll
        for (int p = 0; p < 4; ++p) {
            const float l = c2 - mm[p];
            const float d = l - mx[p];
            const float e = ex2a(0.f - fabsf(d));   // one MUFU per (k,point)
            sm[p] = (d > 0.f) ? fmaf(sm[p], e, 1.f) : (sm[p] + e);
            mx[p] = fmaxf(mx[p], l);
        }
    }

    float acc = 0.f;
    #pragma unroll
    for (int p = 0; p < 2 * NPAIR; ++p)
        acc += mx[p] + lg2a(sm[p]);
    acc *= 0.6931471805599453f;  // back to natural log

    // ---- Stage C: reduce + finalize -----------------------------------------
    red[tid] = acc;
    __syncthreads();
    #pragma unroll
    for (int s = THREADS / 2; s > 0; s >>= 1) {
        if (tid < s) {
            red[tid] += red[tid + s];
            redp[tid] += redp[tid + s];
        }
        __syncthreads();
    }

    if (tid == 0) {
        g_partial[m * CHUNKS + chunk] = red[0];
        __threadfence();
        const int old = atomicAdd(&g_count[m], 1);
        if (old == CHUNKS - 1) {
            __threadfence();
            double s = 0.0;
            #pragma unroll
            for (int c = 0; c < CHUNKS; ++c)
                s += (double)__ldcg(&g_partial[m * CHUNKS + c]);
            out[m] = (float)(-s + 0.005 * (double)redp[0]);  // 0.5*LAMBDA_PRIOR
            g_count[m] = 0;  // self-reset for next launch
        }
    }
}

extern "C" void kernel_launch(void* const* d_in, const int* in_sizes, int n_in,
                              void* d_out, int out_size) {
    const float* phi = (const float*)d_in[0];  // (32, 360)
    const float* X   = (const float*)d_in[1];  // (32768, 8)
    float* out = (float*)d_out;                // (32,)

    fused_kernel<<<M_MODELS * CHUNKS, THREADS>>>(phi, X, out);
}